// round 8
// baseline (speedup 1.0000x reference)
#include <cuda_runtime.h>
#include <cuda_bf16.h>
#include <math.h>

#define NN 50000
#define EE 800000
#define DIN 64
#define DH 128
#define EPSF 1e-5f
#define SLOPEF 0.1f

typedef unsigned long long ull;

// ---------------- scratch (device globals; no allocations) ----------------
__device__ ull   g_degpack[NN];                    // cnt<<42 | fixedpoint(sum ew, 2^26)
__device__ float g_dinv[NN];
__device__ int   g_rowstart[NN + 1];
__device__ int   g_cursor[NN];
__device__ __align__(16) int2  g_edge[EE];         // {src, bits(norm)}
__device__ __align__(16) float g_aggx[(size_t)NN * DIN];
__device__ __align__(16) float g_bufA[(size_t)NN * DH];
__device__ __align__(16) float g_bufB[(size_t)NN * DH];
__device__ __align__(16) float g_bufC[(size_t)NN * DH];
__device__ __align__(16) float g_res [(size_t)NN * DH];
__device__ float g_stats[4 * DH];                  // [sum0, sq0 | sum1, sq1]

// ---------------- f32x2 helpers ----------------
__device__ __forceinline__ void fma2(ull& d, ull a, ull b) {
    asm("fma.rn.f32x2 %0, %1, %2, %0;" : "+l"(d) : "l"(a), "l"(b));
}
__device__ __forceinline__ ull pack2(float a) {
    ull r; asm("mov.b64 %0, {%1, %1};" : "=l"(r) : "f"(a)); return r;
}
__device__ __forceinline__ float2 unpk(ull v) {
    float2 r; asm("mov.b64 {%0, %1}, %2;" : "=f"(r.x), "=f"(r.y) : "l"(v)); return r;
}

// ---------------- init ----------------
__global__ __launch_bounds__(256) void k_init() {
    int i = blockIdx.x * blockDim.x + threadIdx.x;
    if (i < NN) { g_degpack[i] = 0ull; g_cursor[i] = 0; }
    if (i < 4 * DH) g_stats[i] = 0.0f;
}

// ---------------- edge pass 1: packed degree+count, one 64b atomic ----------------
__global__ __launch_bounds__(256) void k_edge1(const int* __restrict__ dst,
                                               const float* __restrict__ ew) {
    int e = blockIdx.x * blockDim.x + threadIdx.x;
    if (e >= EE) return;
    ull add = (1ull << 42) + (ull)__float2uint_rn(ew[e] * 67108864.0f);
    atomicAdd(&g_degpack[dst[e]], add);
}

// ---------------- single-block scan: rowstart, cursors, dinv ----------------
__global__ __launch_bounds__(1024) void k_scan() {
    __shared__ int part[1024];
    int t = threadIdx.x;
    const int chunk = (NN + 1023) / 1024;  // 49
    int start = t * chunk;
    int stop = start + chunk; if (stop > NN) stop = NN; if (start > NN) start = NN;
    int s = 0;
    for (int i = start; i < stop; ++i) {
        ull p = g_degpack[i];
        s += (int)(p >> 42);
        float deg = 1.0f + (float)(p & ((1ull << 42) - 1)) * (1.0f / 67108864.0f);
        g_dinv[i] = rsqrtf(deg);
    }
    part[t] = s;
    __syncthreads();
    for (int off = 1; off < 1024; off <<= 1) {
        int v = (t >= off) ? part[t - off] : 0;
        __syncthreads();
        part[t] += v;
        __syncthreads();
    }
    int run = (t == 0) ? 0 : part[t - 1];
    for (int i = start; i < stop; ++i) {
        int c = (int)(g_degpack[i] >> 42);
        g_rowstart[i] = run;
        g_cursor[i] = run;
        run += c;
    }
    if (t == 1023) g_rowstart[NN] = run;
}

// ---------------- edge pass 2: bucket scatter, single STG.64 ----------------
__global__ __launch_bounds__(256) void k_edge2(const int* __restrict__ src,
                                               const int* __restrict__ dst,
                                               const float* __restrict__ ew) {
    int e = blockIdx.x * blockDim.x + threadIdx.x;
    if (e >= EE) return;
    int s = src[e], d = dst[e];
    float nm = g_dinv[s] * ew[e] * g_dinv[d];
    int p = atomicAdd(&g_cursor[d], 1);
    g_edge[p] = make_int2(s, __float_as_int(nm));
}

// ---------------- agg0: aggregate raw x (64 wide), float2 per lane ----------------
__global__ __launch_bounds__(256) void k_agg0(const float* __restrict__ x) {
    int node = (blockIdx.x * blockDim.x + threadIdx.x) >> 5;
    if (node >= NN) return;
    int lane = threadIdx.x & 31;
    const float2* __restrict__ x2 = (const float2*)x;

    float dv = g_dinv[node];
    float self = dv * dv;
    float2 hv = x2[(size_t)node * 32 + lane];
    float ax = self * hv.x, ay = self * hv.y;

    int e = g_rowstart[node];
    int end = g_rowstart[node + 1];
    for (; e + 4 <= end; e += 4) {
        int2 e0 = g_edge[e + 0], e1 = g_edge[e + 1], e2 = g_edge[e + 2], e3 = g_edge[e + 3];
        float2 v0 = x2[(size_t)e0.x * 32 + lane];
        float2 v1 = x2[(size_t)e1.x * 32 + lane];
        float2 v2 = x2[(size_t)e2.x * 32 + lane];
        float2 v3 = x2[(size_t)e3.x * 32 + lane];
        float w0 = __int_as_float(e0.y), w1 = __int_as_float(e1.y);
        float w2 = __int_as_float(e2.y), w3 = __int_as_float(e3.y);
        ax = fmaf(w0, v0.x, ax); ay = fmaf(w0, v0.y, ay);
        ax = fmaf(w1, v1.x, ax); ay = fmaf(w1, v1.y, ay);
        ax = fmaf(w2, v2.x, ax); ay = fmaf(w2, v2.y, ay);
        ax = fmaf(w3, v3.x, ax); ay = fmaf(w3, v3.y, ay);
    }
    for (; e < end; ++e) {
        int2 ee = g_edge[e];
        float2 v = x2[(size_t)ee.x * 32 + lane];
        float w = __int_as_float(ee.y);
        ax = fmaf(w, v.x, ax); ay = fmaf(w, v.y, ay);
    }
    ((float2*)g_aggx)[(size_t)node * 32 + lane] = make_float2(ax, ay);
}

// ---------------- agg1: aggregate bufA (128 wide), float4 per lane ----------------
__global__ __launch_bounds__(256) void k_agg1() {
    int node = (blockIdx.x * blockDim.x + threadIdx.x) >> 5;
    if (node >= NN) return;
    int lane = threadIdx.x & 31;
    const float4* __restrict__ h4 = (const float4*)g_bufA;

    float dv = g_dinv[node];
    float self = dv * dv;
    float4 hv = h4[(size_t)node * 32 + lane];
    float ax = self * hv.x, ay = self * hv.y, az = self * hv.z, aw = self * hv.w;

    int e = g_rowstart[node];
    int end = g_rowstart[node + 1];
    for (; e + 4 <= end; e += 4) {
        int2 e0 = g_edge[e + 0], e1 = g_edge[e + 1], e2 = g_edge[e + 2], e3 = g_edge[e + 3];
        float4 v0 = h4[(size_t)e0.x * 32 + lane];
        float4 v1 = h4[(size_t)e1.x * 32 + lane];
        float4 v2 = h4[(size_t)e2.x * 32 + lane];
        float4 v3 = h4[(size_t)e3.x * 32 + lane];
        float w0 = __int_as_float(e0.y), w1 = __int_as_float(e1.y);
        float w2 = __int_as_float(e2.y), w3 = __int_as_float(e3.y);
        ax = fmaf(w0, v0.x, ax); ay = fmaf(w0, v0.y, ay); az = fmaf(w0, v0.z, az); aw = fmaf(w0, v0.w, aw);
        ax = fmaf(w1, v1.x, ax); ay = fmaf(w1, v1.y, ay); az = fmaf(w1, v1.z, az); aw = fmaf(w1, v1.w, aw);
        ax = fmaf(w2, v2.x, ax); ay = fmaf(w2, v2.y, ay); az = fmaf(w2, v2.z, az); aw = fmaf(w2, v2.w, aw);
        ax = fmaf(w3, v3.x, ax); ay = fmaf(w3, v3.y, ay); az = fmaf(w3, v3.z, az); aw = fmaf(w3, v3.w, aw);
    }
    for (; e < end; ++e) {
        int2 ee = g_edge[e];
        float4 v = h4[(size_t)ee.x * 32 + lane];
        float w = __int_as_float(ee.y);
        ax = fmaf(w, v.x, ax); ay = fmaf(w, v.y, ay);
        az = fmaf(w, v.z, az); aw = fmaf(w, v.w, aw);
    }
    ((float4*)g_bufC)[(size_t)node * 32 + lane] = make_float4(ax, ay, az, aw);
}

// ---------------- GEMM: C[N x 128] = A[N x K] @ B[K x 128] + bias, f32x2 core ----------------
// 64x128 block tile, 256 threads as 16x16; thread = 4 rows x 8 cols.
// Asel: 0=ext, 1=g_aggx, 2=g_bufC.  Csel: 0=g_bufB, 1=g_res.
// Stats arrays alias As (dead after mainloop) to stay within 48 KB static smem.
template <int K, bool STATS>
__global__ __launch_bounds__(256) void k_gemm2(const float* __restrict__ Aext, int Asel,
                                               const float* __restrict__ B,
                                               const float* __restrict__ bias,
                                               int Csel, int soff) {
    __shared__ float Bs[64 * DH];    // 32 KB
    __shared__ float As[64 * 64];    // 16 KB (reused for stats post-loop)
    const float* __restrict__ A = (Asel == 0) ? Aext : ((Asel == 1) ? g_aggx : g_bufC);
    float* C = (Csel == 0) ? g_bufB : g_res;
    int t = threadIdx.x;
    int tx = t & 15, ty = t >> 4;
    int row0 = blockIdx.x * 64;

    ull acc[4][4];
#pragma unroll
    for (int j = 0; j < 4; j++)
#pragma unroll
        for (int i = 0; i < 4; i++) acc[j][i] = 0ull;

    for (int kc = 0; kc < K / 64; kc++) {
        const float4* Bsrc = (const float4*)(B + (size_t)kc * 64 * DH);
        for (int i = t; i < 64 * DH / 4; i += 256) ((float4*)Bs)[i] = Bsrc[i];
        for (int i = t; i < 64 * 64 / 4; i += 256) {
            int r = i >> 4, c = i & 15;
            int gr = row0 + r;
            float4 v = make_float4(0.f, 0.f, 0.f, 0.f);
            if (gr < NN) v = *(const float4*)(A + (size_t)gr * K + kc * 64 + c * 4);
            ((float4*)As)[i] = v;
        }
        __syncthreads();
        const ulonglong2* Bs2 = (const ulonglong2*)Bs;   // 32 ulonglong2 per 128-float row
        const float* Ar = As + ty * 4 * 64;
#pragma unroll 8
        for (int k = 0; k < 64; k++) {
            ulonglong2 q0 = Bs2[k * 32 + tx * 2];
            ulonglong2 q1 = Bs2[k * 32 + tx * 2 + 1];
#pragma unroll
            for (int j = 0; j < 4; j++) {
                ull ap = pack2(Ar[j * 64 + k]);   // warp-broadcast LDS
                fma2(acc[j][0], ap, q0.x);
                fma2(acc[j][1], ap, q0.y);
                fma2(acc[j][2], ap, q1.x);
                fma2(acc[j][3], ap, q1.y);
            }
        }
        __syncthreads();
    }

    // stats arrays alias As (mainloop is done; last __syncthreads already passed)
    float* ssum = As;
    float* ssq  = As + DH;
    if (STATS) {
        if (t < DH) { ssum[t] = 0.f; ssq[t] = 0.f; }
        __syncthreads();
    }

    float4 bv0 = ((const float4*)bias)[tx * 2];
    float4 bv1 = ((const float4*)bias)[tx * 2 + 1];
    float ps[8], pq[8];
#pragma unroll
    for (int c = 0; c < 8; c++) { ps[c] = 0.f; pq[c] = 0.f; }

#pragma unroll
    for (int j = 0; j < 4; j++) {
        int gr = row0 + ty * 4 + j;
        if (gr >= NN) continue;
        float2 u0 = unpk(acc[j][0]), u1 = unpk(acc[j][1]);
        float2 u2 = unpk(acc[j][2]), u3 = unpk(acc[j][3]);
        float o0 = u0.x + bv0.x, o1 = u0.y + bv0.y, o2 = u1.x + bv0.z, o3 = u1.y + bv0.w;
        float o4 = u2.x + bv1.x, o5 = u2.y + bv1.y, o6 = u3.x + bv1.z, o7 = u3.y + bv1.w;
        float* cp = C + (size_t)gr * DH + tx * 8;
        *(float4*)cp       = make_float4(o0, o1, o2, o3);
        *(float4*)(cp + 4) = make_float4(o4, o5, o6, o7);
        if (STATS) {
            ps[0] += o0; pq[0] = fmaf(o0, o0, pq[0]);
            ps[1] += o1; pq[1] = fmaf(o1, o1, pq[1]);
            ps[2] += o2; pq[2] = fmaf(o2, o2, pq[2]);
            ps[3] += o3; pq[3] = fmaf(o3, o3, pq[3]);
            ps[4] += o4; pq[4] = fmaf(o4, o4, pq[4]);
            ps[5] += o5; pq[5] = fmaf(o5, o5, pq[5]);
            ps[6] += o6; pq[6] = fmaf(o6, o6, pq[6]);
            ps[7] += o7; pq[7] = fmaf(o7, o7, pq[7]);
        }
    }
    if (STATS) {
#pragma unroll
        for (int c = 0; c < 8; c++) {
            atomicAdd(&ssum[tx * 8 + c], ps[c]);
            atomicAdd(&ssq[tx * 8 + c], pq[c]);
        }
        __syncthreads();
        if (t < DH) {
            atomicAdd(&g_stats[soff + t], ssum[t]);
            atomicAdd(&g_stats[soff + DH + t], ssq[t]);
        }
    }
}

// ---------------- layer-0 epilogue: BN + leaky + residual -> bufA ----------------
__global__ __launch_bounds__(256) void k_apply0(const float* __restrict__ gam,
                                                const float* __restrict__ bet) {
    __shared__ float sc[DH], sh[DH];
    int t = threadIdx.x;
    if (t < DH) {
        float mu = g_stats[t] * (1.0f / NN);
        float ex2 = g_stats[DH + t] * (1.0f / NN);
        float var = ex2 - mu * mu;
        float s = rsqrtf(var + EPSF) * gam[t];
        sc[t] = s;
        sh[t] = fmaf(-mu, s, bet[t]);
    }
    __syncthreads();
    int idx = blockIdx.x * blockDim.x + t;
    if (idx >= NN * 32) return;
    int f = (idx & 31) * 4;
    float4 v = ((const float4*)g_bufB)[idx];
    float4 r = ((const float4*)g_res)[idx];
    float x0 = fmaf(v.x, sc[f + 0], sh[f + 0]); x0 = (x0 >= 0.f) ? x0 : SLOPEF * x0; x0 += r.x;
    float x1 = fmaf(v.y, sc[f + 1], sh[f + 1]); x1 = (x1 >= 0.f) ? x1 : SLOPEF * x1; x1 += r.y;
    float x2 = fmaf(v.z, sc[f + 2], sh[f + 2]); x2 = (x2 >= 0.f) ? x2 : SLOPEF * x2; x2 += r.z;
    float x3 = fmaf(v.w, sc[f + 3], sh[f + 3]); x3 = (x3 >= 0.f) ? x3 : SLOPEF * x3; x3 += r.w;
    ((float4*)g_bufA)[idx] = make_float4(x0, x1, x2, x3);
}

// ---------------- final: BN + leaky + residual + row LayerNorm -> out ----------------
__global__ __launch_bounds__(256) void k_final(const float* __restrict__ gam,
                                               const float* __restrict__ bet,
                                               float* __restrict__ out) {
    __shared__ float sc[DH], sh[DH];
    int t = threadIdx.x;
    if (t < DH) {
        float mu = g_stats[2 * DH + t] * (1.0f / NN);
        float ex2 = g_stats[3 * DH + t] * (1.0f / NN);
        float var = ex2 - mu * mu;
        float s = rsqrtf(var + EPSF) * gam[t];
        sc[t] = s;
        sh[t] = fmaf(-mu, s, bet[t]);
    }
    __syncthreads();
    int node = blockIdx.x * 8 + (t >> 5);
    if (node >= NN) return;
    int lane = t & 31;
    float4 v = ((const float4*)g_bufB)[(size_t)node * 32 + lane];
    float4 r = ((const float4*)g_res)[(size_t)node * 32 + lane];
    int f = lane * 4;
    float x0 = fmaf(v.x, sc[f + 0], sh[f + 0]); x0 = (x0 >= 0.f) ? x0 : SLOPEF * x0; x0 += r.x;
    float x1 = fmaf(v.y, sc[f + 1], sh[f + 1]); x1 = (x1 >= 0.f) ? x1 : SLOPEF * x1; x1 += r.y;
    float x2 = fmaf(v.z, sc[f + 2], sh[f + 2]); x2 = (x2 >= 0.f) ? x2 : SLOPEF * x2; x2 += r.z;
    float x3 = fmaf(v.w, sc[f + 3], sh[f + 3]); x3 = (x3 >= 0.f) ? x3 : SLOPEF * x3; x3 += r.w;
    float s1 = x0 + x1 + x2 + x3;
    float s2 = x0 * x0 + x1 * x1 + x2 * x2 + x3 * x3;
#pragma unroll
    for (int off = 16; off; off >>= 1) {
        s1 += __shfl_xor_sync(0xFFFFFFFFu, s1, off);
        s2 += __shfl_xor_sync(0xFFFFFFFFu, s2, off);
    }
    float mu = s1 * (1.0f / DH);
    float var = s2 * (1.0f / DH) - mu * mu;
    float rs = rsqrtf(var + EPSF);
    ((float4*)out)[(size_t)node * 32 + lane] =
        make_float4((x0 - mu) * rs, (x1 - mu) * rs, (x2 - mu) * rs, (x3 - mu) * rs);
}

// ---------------- launch ----------------
extern "C" void kernel_launch(void* const* d_in, const int* in_sizes, int n_in,
                              void* d_out, int out_size) {
    const float* x    = (const float*)d_in[0];
    const int*   src  = (const int*)d_in[1];
    const int*   dst  = (const int*)d_in[2];
    const float* ew   = (const float*)d_in[3];
    const float* W0   = (const float*)d_in[4];
    const float* b0   = (const float*)d_in[5];
    const float* g0   = (const float*)d_in[6];
    const float* be0  = (const float*)d_in[7];
    const float* W1   = (const float*)d_in[8];
    const float* b1   = (const float*)d_in[9];
    const float* g1   = (const float*)d_in[10];
    const float* be1  = (const float*)d_in[11];
    const float* Wres = (const float*)d_in[12];
    const float* bres = (const float*)d_in[13];
    float* out = (float*)d_out;

    const int gridN = (NN + 255) / 256;
    const int gridE = (EE + 255) / 256;
    const int gridG = (NN + 63) / 64;        // 782 gemm blocks
    const int gridW = (NN * 32 + 255) / 256; // warp-per-node kernels
    const int gridV = (NN * 32 + 255) / 256; // float4 elementwise

    // graph preprocessing
    k_init <<<gridN, 256>>>();
    k_edge1<<<gridE, 256>>>(dst, ew);
    k_scan <<<1, 1024>>>();
    k_edge2<<<gridE, 256>>>(src, dst, ew);

    // layer 0: aggregate-first (64-wide), then transform (+fused BN stats)
    k_agg0<<<gridW, 256>>>(x);                                   // aggx = Agg(x)
    k_gemm2<DIN, true ><<<gridG, 256>>>(nullptr, 1, W0, b0, 0, 0);     // bufB = aggx@W0+b0, stats0
    k_gemm2<DIN, false><<<gridG, 256>>>(x, 0, Wres, bres, 1, 0);       // res  = x@Wres+bres
    k_apply0<<<gridV, 256>>>(g0, be0);                           // bufA = act(bn(bufB)) + res

    // layer 1: aggregate-first (128-wide), then transform (+fused BN stats)
    k_agg1<<<gridW, 256>>>();                                    // bufC = Agg(bufA)
    k_gemm2<DH, true><<<gridG, 256>>>(nullptr, 2, W1, b1, 0, 2 * DH);  // bufB = bufC@W1+b1, stats1
    k_final<<<gridW, 256>>>(g1, be1, out);                       // out = LN(act(bn(bufB)) + res)
}

// round 9
// speedup vs baseline: 1.1987x; 1.1987x over previous
#include <cuda_runtime.h>
#include <cuda_bf16.h>
#include <math.h>

#define NN 50000
#define EE 800000
#define DIN 64
#define DH 128
#define EPSF 1e-5f
#define SLOPEF 0.1f

typedef unsigned long long ull;

// edge kernels: 4 edges per thread, grid-strided
#define EBLK 782
#define ESTRIDE (EBLK * 256)   // 200192

// ---------------- scratch (device globals; no allocations) ----------------
__device__ ull   g_degpack[NN];                    // cnt<<42 | fixedpoint(sum ew, 2^26)
__device__ float g_dinv[NN];
__device__ int   g_rowstart[NN + 1];
__device__ int   g_cursor[NN];
__device__ __align__(16) int2  g_edge[EE];         // {src, bits(norm)}
__device__ __align__(16) float g_aggx[(size_t)NN * DIN];
__device__ __align__(16) float g_bufA[(size_t)NN * DH];
__device__ __align__(16) float g_bufB[(size_t)NN * DH];
__device__ __align__(16) float g_bufC[(size_t)NN * DH];
__device__ __align__(16) float g_res [(size_t)NN * DH];
__device__ float g_stats[4 * DH];                  // [sum0, sq0 | sum1, sq1]

// ---------------- init ----------------
__global__ __launch_bounds__(256) void k_init() {
    int i = blockIdx.x * blockDim.x + threadIdx.x;
    if (i < NN) { g_degpack[i] = 0ull; g_cursor[i] = 0; }
    if (i < 4 * DH) g_stats[i] = 0.0f;
}

// ---------------- edge pass 1: packed degree+count, 4 edges/thread ----------------
__global__ __launch_bounds__(256) void k_edge1(const int* __restrict__ dst,
                                               const float* __restrict__ ew) {
    int e = blockIdx.x * 256 + threadIdx.x;
    // e < 200192; e+2*ESTRIDE < 800000 always; guard only the last
    int d0 = dst[e], d1 = dst[e + ESTRIDE], d2 = dst[e + 2 * ESTRIDE];
    float w0 = ew[e], w1 = ew[e + ESTRIDE], w2 = ew[e + 2 * ESTRIDE];
    int e3 = e + 3 * ESTRIDE;
    int d3 = 0; float w3 = 0.f;
    bool has3 = (e3 < EE);
    if (has3) { d3 = dst[e3]; w3 = ew[e3]; }
    ull a0 = (1ull << 42) + (ull)__float2uint_rn(w0 * 67108864.0f);
    ull a1 = (1ull << 42) + (ull)__float2uint_rn(w1 * 67108864.0f);
    ull a2 = (1ull << 42) + (ull)__float2uint_rn(w2 * 67108864.0f);
    atomicAdd(&g_degpack[d0], a0);
    atomicAdd(&g_degpack[d1], a1);
    atomicAdd(&g_degpack[d2], a2);
    if (has3) {
        ull a3 = (1ull << 42) + (ull)__float2uint_rn(w3 * 67108864.0f);
        atomicAdd(&g_degpack[d3], a3);
    }
}

// ---------------- single-block scan: rowstart, cursors, dinv ----------------
__global__ __launch_bounds__(1024) void k_scan() {
    __shared__ int part[1024];
    int t = threadIdx.x;
    const int chunk = (NN + 1023) / 1024;  // 49
    int start = t * chunk;
    int stop = start + chunk; if (stop > NN) stop = NN; if (start > NN) start = NN;
    int s = 0;
#pragma unroll 4
    for (int i = start; i < stop; ++i) {
        ull p = g_degpack[i];
        s += (int)(p >> 42);
        float deg = 1.0f + (float)(p & ((1ull << 42) - 1)) * (1.0f / 67108864.0f);
        g_dinv[i] = rsqrtf(deg);
    }
    part[t] = s;
    __syncthreads();
    for (int off = 1; off < 1024; off <<= 1) {
        int v = (t >= off) ? part[t - off] : 0;
        __syncthreads();
        part[t] += v;
        __syncthreads();
    }
    int run = (t == 0) ? 0 : part[t - 1];
#pragma unroll 4
    for (int i = start; i < stop; ++i) {
        int c = (int)(g_degpack[i] >> 42);
        g_rowstart[i] = run;
        g_cursor[i] = run;
        run += c;
    }
    if (t == 1023) g_rowstart[NN] = run;
}

// ---------------- edge pass 2: bucket scatter, 4 edges/thread ----------------
__global__ __launch_bounds__(256) void k_edge2(const int* __restrict__ src,
                                               const int* __restrict__ dst,
                                               const float* __restrict__ ew) {
    int e = blockIdx.x * 256 + threadIdx.x;
    int e1 = e + ESTRIDE, e2 = e + 2 * ESTRIDE, e3 = e + 3 * ESTRIDE;
    bool has3 = (e3 < EE);
    int s0 = src[e],  d0 = dst[e];
    int s1 = src[e1], d1 = dst[e1];
    int s2 = src[e2], d2 = dst[e2];
    int s3 = 0, d3 = 0;
    if (has3) { s3 = src[e3]; d3 = dst[e3]; }
    float w0 = ew[e], w1 = ew[e1], w2 = ew[e2], w3 = has3 ? ew[e3] : 0.f;
    float n0 = g_dinv[s0] * w0 * g_dinv[d0];
    float n1 = g_dinv[s1] * w1 * g_dinv[d1];
    float n2 = g_dinv[s2] * w2 * g_dinv[d2];
    int p0 = atomicAdd(&g_cursor[d0], 1);
    int p1 = atomicAdd(&g_cursor[d1], 1);
    int p2 = atomicAdd(&g_cursor[d2], 1);
    g_edge[p0] = make_int2(s0, __float_as_int(n0));
    g_edge[p1] = make_int2(s1, __float_as_int(n1));
    g_edge[p2] = make_int2(s2, __float_as_int(n2));
    if (has3) {
        float n3 = g_dinv[s3] * w3 * g_dinv[d3];
        int p3 = atomicAdd(&g_cursor[d3], 1);
        g_edge[p3] = make_int2(s3, __float_as_int(n3));
    }
}

// ---------------- agg0: aggregate raw x (64 wide), float2 per lane ----------------
__global__ __launch_bounds__(256) void k_agg0(const float* __restrict__ x) {
    int node = (blockIdx.x * blockDim.x + threadIdx.x) >> 5;
    if (node >= NN) return;
    int lane = threadIdx.x & 31;
    const float2* __restrict__ x2 = (const float2*)x;

    float dv = g_dinv[node];
    float self = dv * dv;
    float2 hv = x2[(size_t)node * 32 + lane];
    float ax = self * hv.x, ay = self * hv.y;

    int e = g_rowstart[node];
    int end = g_rowstart[node + 1];
    for (; e + 4 <= end; e += 4) {
        int2 e0 = g_edge[e + 0], e1 = g_edge[e + 1], e2 = g_edge[e + 2], e3 = g_edge[e + 3];
        float2 v0 = x2[(size_t)e0.x * 32 + lane];
        float2 v1 = x2[(size_t)e1.x * 32 + lane];
        float2 v2 = x2[(size_t)e2.x * 32 + lane];
        float2 v3 = x2[(size_t)e3.x * 32 + lane];
        float w0 = __int_as_float(e0.y), w1 = __int_as_float(e1.y);
        float w2 = __int_as_float(e2.y), w3 = __int_as_float(e3.y);
        ax = fmaf(w0, v0.x, ax); ay = fmaf(w0, v0.y, ay);
        ax = fmaf(w1, v1.x, ax); ay = fmaf(w1, v1.y, ay);
        ax = fmaf(w2, v2.x, ax); ay = fmaf(w2, v2.y, ay);
        ax = fmaf(w3, v3.x, ax); ay = fmaf(w3, v3.y, ay);
    }
    for (; e < end; ++e) {
        int2 ee = g_edge[e];
        float2 v = x2[(size_t)ee.x * 32 + lane];
        float w = __int_as_float(ee.y);
        ax = fmaf(w, v.x, ax); ay = fmaf(w, v.y, ay);
    }
    ((float2*)g_aggx)[(size_t)node * 32 + lane] = make_float2(ax, ay);
}

// ---------------- agg1: aggregate bufA (128 wide), float4 per lane ----------------
__global__ __launch_bounds__(256) void k_agg1() {
    int node = (blockIdx.x * blockDim.x + threadIdx.x) >> 5;
    if (node >= NN) return;
    int lane = threadIdx.x & 31;
    const float4* __restrict__ h4 = (const float4*)g_bufA;

    float dv = g_dinv[node];
    float self = dv * dv;
    float4 hv = h4[(size_t)node * 32 + lane];
    float ax = self * hv.x, ay = self * hv.y, az = self * hv.z, aw = self * hv.w;

    int e = g_rowstart[node];
    int end = g_rowstart[node + 1];
    for (; e + 4 <= end; e += 4) {
        int2 e0 = g_edge[e + 0], e1 = g_edge[e + 1], e2 = g_edge[e + 2], e3 = g_edge[e + 3];
        float4 v0 = h4[(size_t)e0.x * 32 + lane];
        float4 v1 = h4[(size_t)e1.x * 32 + lane];
        float4 v2 = h4[(size_t)e2.x * 32 + lane];
        float4 v3 = h4[(size_t)e3.x * 32 + lane];
        float w0 = __int_as_float(e0.y), w1 = __int_as_float(e1.y);
        float w2 = __int_as_float(e2.y), w3 = __int_as_float(e3.y);
        ax = fmaf(w0, v0.x, ax); ay = fmaf(w0, v0.y, ay); az = fmaf(w0, v0.z, az); aw = fmaf(w0, v0.w, aw);
        ax = fmaf(w1, v1.x, ax); ay = fmaf(w1, v1.y, ay); az = fmaf(w1, v1.z, az); aw = fmaf(w1, v1.w, aw);
        ax = fmaf(w2, v2.x, ax); ay = fmaf(w2, v2.y, ay); az = fmaf(w2, v2.z, az); aw = fmaf(w2, v2.w, aw);
        ax = fmaf(w3, v3.x, ax); ay = fmaf(w3, v3.y, ay); az = fmaf(w3, v3.z, az); aw = fmaf(w3, v3.w, aw);
    }
    for (; e < end; ++e) {
        int2 ee = g_edge[e];
        float4 v = h4[(size_t)ee.x * 32 + lane];
        float w = __int_as_float(ee.y);
        ax = fmaf(w, v.x, ax); ay = fmaf(w, v.y, ay);
        az = fmaf(w, v.z, az); aw = fmaf(w, v.w, aw);
    }
    ((float4*)g_bufC)[(size_t)node * 32 + lane] = make_float4(ax, ay, az, aw);
}

// ---------------- GEMM: C[N x 128] = A[N x K] @ B[K x 128] + bias ----------------
// R3-proven core: 64x128 block tile, 256 threads (8 warps), thread = 8 rows x 4 cols.
// Optional fused BN stats epilogue; stats arrays alias As (dead after mainloop).
// Asel: 0=ext, 1=g_aggx, 2=g_bufC.  Csel: 0=g_bufB, 1=g_res.
template <int K, bool STATS>
__global__ __launch_bounds__(256) void k_gemm(const float* __restrict__ Aext, int Asel,
                                              const float* __restrict__ B,
                                              const float* __restrict__ bias,
                                              int Csel, int soff) {
    __shared__ float Bs[64 * DH];   // 32 KB
    __shared__ float As[64 * 64];   // 16 KB (reused for stats post-loop)
    const float* __restrict__ A = (Asel == 0) ? Aext : ((Asel == 1) ? g_aggx : g_bufC);
    float* C = (Csel == 0) ? g_bufB : g_res;
    int t = threadIdx.x;
    int row0 = blockIdx.x * 64;
    int lane = t & 31, w = t >> 5;
    float4 acc[8];
#pragma unroll
    for (int j = 0; j < 8; j++) acc[j] = make_float4(0.f, 0.f, 0.f, 0.f);

    for (int kc = 0; kc < K / 64; kc++) {
        const float4* Bsrc = (const float4*)(B + (size_t)kc * 64 * DH);
        for (int i = t; i < 64 * DH / 4; i += 256) ((float4*)Bs)[i] = Bsrc[i];
        for (int i = t; i < 64 * 64 / 4; i += 256) {
            int r = i >> 4, c = i & 15;
            int gr = row0 + r;
            float4 v = make_float4(0.f, 0.f, 0.f, 0.f);
            if (gr < NN) v = *(const float4*)(A + (size_t)gr * K + kc * 64 + c * 4);
            ((float4*)As)[i] = v;
        }
        __syncthreads();
        const float* Ar = As + w * 8 * 64;
#pragma unroll 4
        for (int k = 0; k < 64; k++) {
            float4 b = *(const float4*)(Bs + k * DH + lane * 4);
#pragma unroll
            for (int j = 0; j < 8; j++) {
                float a = Ar[j * 64 + k];   // warp-broadcast LDS
                acc[j].x = fmaf(a, b.x, acc[j].x);
                acc[j].y = fmaf(a, b.y, acc[j].y);
                acc[j].z = fmaf(a, b.z, acc[j].z);
                acc[j].w = fmaf(a, b.w, acc[j].w);
            }
        }
        __syncthreads();
    }

    // stats arrays alias As (mainloop done; last __syncthreads passed)
    float* ssum = As;
    float* ssq  = As + DH;
    if (STATS) {
        if (t < DH) { ssum[t] = 0.f; ssq[t] = 0.f; }
        __syncthreads();
    }

    float4 bv = ((const float4*)bias)[lane];
    float ps[4], pq[4];
#pragma unroll
    for (int c = 0; c < 4; c++) { ps[c] = 0.f; pq[c] = 0.f; }

#pragma unroll
    for (int j = 0; j < 8; j++) {
        int gr = row0 + w * 8 + j;
        if (gr >= NN) continue;
        float o0 = acc[j].x + bv.x, o1 = acc[j].y + bv.y;
        float o2 = acc[j].z + bv.z, o3 = acc[j].w + bv.w;
        *(float4*)(C + (size_t)gr * DH + lane * 4) = make_float4(o0, o1, o2, o3);
        if (STATS) {
            ps[0] += o0; pq[0] = fmaf(o0, o0, pq[0]);
            ps[1] += o1; pq[1] = fmaf(o1, o1, pq[1]);
            ps[2] += o2; pq[2] = fmaf(o2, o2, pq[2]);
            ps[3] += o3; pq[3] = fmaf(o3, o3, pq[3]);
        }
    }
    if (STATS) {
#pragma unroll
        for (int c = 0; c < 4; c++) {
            atomicAdd(&ssum[lane * 4 + c], ps[c]);
            atomicAdd(&ssq[lane * 4 + c], pq[c]);
        }
        __syncthreads();
        if (t < DH) {
            atomicAdd(&g_stats[soff + t], ssum[t]);
            atomicAdd(&g_stats[soff + DH + t], ssq[t]);
        }
    }
}

// ---------------- layer-0 epilogue: BN + leaky + residual -> bufA ----------------
__global__ __launch_bounds__(256) void k_apply0(const float* __restrict__ gam,
                                                const float* __restrict__ bet) {
    __shared__ float sc[DH], sh[DH];
    int t = threadIdx.x;
    if (t < DH) {
        float mu = g_stats[t] * (1.0f / NN);
        float ex2 = g_stats[DH + t] * (1.0f / NN);
        float var = ex2 - mu * mu;
        float s = rsqrtf(var + EPSF) * gam[t];
        sc[t] = s;
        sh[t] = fmaf(-mu, s, bet[t]);
    }
    __syncthreads();
    int idx = blockIdx.x * blockDim.x + t;
    if (idx >= NN * 32) return;
    int f = (idx & 31) * 4;
    float4 v = ((const float4*)g_bufB)[idx];
    float4 r = ((const float4*)g_res)[idx];
    float x0 = fmaf(v.x, sc[f + 0], sh[f + 0]); x0 = (x0 >= 0.f) ? x0 : SLOPEF * x0; x0 += r.x;
    float x1 = fmaf(v.y, sc[f + 1], sh[f + 1]); x1 = (x1 >= 0.f) ? x1 : SLOPEF * x1; x1 += r.y;
    float x2 = fmaf(v.z, sc[f + 2], sh[f + 2]); x2 = (x2 >= 0.f) ? x2 : SLOPEF * x2; x2 += r.z;
    float x3 = fmaf(v.w, sc[f + 3], sh[f + 3]); x3 = (x3 >= 0.f) ? x3 : SLOPEF * x3; x3 += r.w;
    ((float4*)g_bufA)[idx] = make_float4(x0, x1, x2, x3);
}

// ---------------- final: BN + leaky + residual + row LayerNorm -> out ----------------
__global__ __launch_bounds__(256) void k_final(const float* __restrict__ gam,
                                               const float* __restrict__ bet,
                                               float* __restrict__ out) {
    __shared__ float sc[DH], sh[DH];
    int t = threadIdx.x;
    if (t < DH) {
        float mu = g_stats[2 * DH + t] * (1.0f / NN);
        float ex2 = g_stats[3 * DH + t] * (1.0f / NN);
        float var = ex2 - mu * mu;
        float s = rsqrtf(var + EPSF) * gam[t];
        sc[t] = s;
        sh[t] = fmaf(-mu, s, bet[t]);
    }
    __syncthreads();
    int node = blockIdx.x * 8 + (t >> 5);
    if (node >= NN) return;
    int lane = t & 31;
    float4 v = ((const float4*)g_bufB)[(size_t)node * 32 + lane];
    float4 r = ((const float4*)g_res)[(size_t)node * 32 + lane];
    int f = lane * 4;
    float x0 = fmaf(v.x, sc[f + 0], sh[f + 0]); x0 = (x0 >= 0.f) ? x0 : SLOPEF * x0; x0 += r.x;
    float x1 = fmaf(v.y, sc[f + 1], sh[f + 1]); x1 = (x1 >= 0.f) ? x1 : SLOPEF * x1; x1 += r.y;
    float x2 = fmaf(v.z, sc[f + 2], sh[f + 2]); x2 = (x2 >= 0.f) ? x2 : SLOPEF * x2; x2 += r.z;
    float x3 = fmaf(v.w, sc[f + 3], sh[f + 3]); x3 = (x3 >= 0.f) ? x3 : SLOPEF * x3; x3 += r.w;
    float s1 = x0 + x1 + x2 + x3;
    float s2 = x0 * x0 + x1 * x1 + x2 * x2 + x3 * x3;
#pragma unroll
    for (int off = 16; off; off >>= 1) {
        s1 += __shfl_xor_sync(0xFFFFFFFFu, s1, off);
        s2 += __shfl_xor_sync(0xFFFFFFFFu, s2, off);
    }
    float mu = s1 * (1.0f / DH);
    float var = s2 * (1.0f / DH) - mu * mu;
    float rs = rsqrtf(var + EPSF);
    ((float4*)out)[(size_t)node * 32 + lane] =
        make_float4((x0 - mu) * rs, (x1 - mu) * rs, (x2 - mu) * rs, (x3 - mu) * rs);
}

// ---------------- launch ----------------
extern "C" void kernel_launch(void* const* d_in, const int* in_sizes, int n_in,
                              void* d_out, int out_size) {
    const float* x    = (const float*)d_in[0];
    const int*   src  = (const int*)d_in[1];
    const int*   dst  = (const int*)d_in[2];
    const float* ew   = (const float*)d_in[3];
    const float* W0   = (const float*)d_in[4];
    const float* b0   = (const float*)d_in[5];
    const float* g0   = (const float*)d_in[6];
    const float* be0  = (const float*)d_in[7];
    const float* W1   = (const float*)d_in[8];
    const float* b1   = (const float*)d_in[9];
    const float* g1   = (const float*)d_in[10];
    const float* be1  = (const float*)d_in[11];
    const float* Wres = (const float*)d_in[12];
    const float* bres = (const float*)d_in[13];
    float* out = (float*)d_out;

    const int gridN = (NN + 255) / 256;
    const int gridG = (NN + 63) / 64;        // 782 gemm blocks
    const int gridW = (NN * 32 + 255) / 256; // warp-per-node kernels
    const int gridV = (NN * 32 + 255) / 256; // float4 elementwise

    // graph preprocessing
    k_init <<<gridN, 256>>>();
    k_edge1<<<EBLK, 256>>>(dst, ew);
    k_scan <<<1, 1024>>>();
    k_edge2<<<EBLK, 256>>>(src, dst, ew);

    // layer 0: aggregate-first (64-wide), then transform (+fused BN stats)
    k_agg0<<<gridW, 256>>>(x);                                  // aggx = Agg(x)
    k_gemm<DIN, true ><<<gridG, 256>>>(nullptr, 1, W0, b0, 0, 0);    // bufB = aggx@W0+b0, stats0
    k_gemm<DIN, false><<<gridG, 256>>>(x, 0, Wres, bres, 1, 0);      // res  = x@Wres+bres
    k_apply0<<<gridV, 256>>>(g0, be0);                          // bufA = act(bn(bufB)) + res

    // layer 1: aggregate-first (128-wide), then transform (+fused BN stats)
    k_agg1<<<gridW, 256>>>();                                   // bufC = Agg(bufA)
    k_gemm<DH, true><<<gridG, 256>>>(nullptr, 2, W1, b1, 0, 2 * DH); // bufB = bufC@W1+b1, stats1
    k_final<<<gridW, 256>>>(g1, be1, out);                      // out = LN(act(bn(bufB)) + res)
}